// round 3
// baseline (speedup 1.0000x reference)
#include <cuda_runtime.h>
#include <math.h>
#include <cstdint>

// Problem constants
#define E_TOTAL  160000
#define NNODES   10000
#define TE1      32      // rows per block, kernel 1
#define TE2      64      // edges per block, kernel 2

#define INV_SQRT3 0.5773502691896258f
#define ALPHA     0.17677669529663687f   // 1/sqrt(32)

typedef unsigned long long ull;

// Scratch (device globals: no allocation allowed)
__device__ float g_h[(size_t)E_TOTAL * 128];   // gelu(emb@W1+b1), 82 MB
__device__ float g_cnt[NNODES];

// ---------------------------------------------------------------------------
// packed f32x2 helpers (Blackwell): ptxas won't auto-fuse, must use PTX
// ---------------------------------------------------------------------------
__device__ __forceinline__ ull ffma2(ull a, ull b, ull c) {
    ull d;
    asm("fma.rn.f32x2 %0, %1, %2, %3;" : "=l"(d) : "l"(a), "l"(b), "l"(c));
    return d;
}
__device__ __forceinline__ ull pack2(float x, float y) {
    return (ull)__float_as_uint(x) | ((ull)__float_as_uint(y) << 32);
}
__device__ __forceinline__ float lo2(ull a) { return __uint_as_float((unsigned)a); }
__device__ __forceinline__ float hi2(ull a) { return __uint_as_float((unsigned)(a >> 32)); }

__device__ __forceinline__ float gelu_exact(float x) {
    return 0.5f * x * (1.0f + erff(x * 0.7071067811865476f));
}

// ---------------------------------------------------------------------------
// Kernel 0: zero output accumulator + counts
// ---------------------------------------------------------------------------
__global__ void k_zero(float* __restrict__ out) {
    int i = blockIdx.x * blockDim.x + threadIdx.x;
    if (i < NNODES * 64) out[i] = 0.0f;
    if (i < NNODES) g_cnt[i] = 0.0f;
}

// ---------------------------------------------------------------------------
// Kernel 1: h = gelu(emb @ W1 + b1)   [160000 x 128] = [.. x128]@[128x128]
// Block: 32 rows, 256 threads. W1 fully staged in smem (64 KB).
// Thread (r = tid>>3, u = tid&7) owns cols {4u + 32i + j : i<4, j<4}
// -> per LDS.128 instruction lanes hit banks 4u..4u+3: conflict-free.
// ---------------------------------------------------------------------------
__global__ void __launch_bounds__(256)
k_mlp1(const float* __restrict__ emb, const float* __restrict__ W1,
       const float* __restrict__ b1) {
    extern __shared__ float smem[];
    float* W1s  = smem;               // 128*128
    float* embs = smem + 128 * 128;   // 32*128
    int tid = threadIdx.x;
    size_t rowBase = (size_t)blockIdx.x * TE1;

    {   // stage W1 (coalesced)
        const float4* Wv = (const float4*)W1;
        float4* Wsv = (float4*)W1s;
#pragma unroll
        for (int it = 0; it < 16; it++) Wsv[it * 256 + tid] = Wv[it * 256 + tid];
        // stage emb tile
        const float4* ev = (const float4*)(emb + rowBase * 128);
        float4* esv = (float4*)embs;
#pragma unroll
        for (int it = 0; it < 4; it++) esv[it * 256 + tid] = ev[it * 256 + tid];
    }
    __syncthreads();

    int r = tid >> 3;
    int u = tid & 7;
    ull acc[8];
#pragma unroll
    for (int i = 0; i < 4; i++) {
        const float* bp = b1 + 4 * u + 32 * i;
        acc[2 * i]     = pack2(__ldg(bp + 0), __ldg(bp + 1));
        acc[2 * i + 1] = pack2(__ldg(bp + 2), __ldg(bp + 3));
    }
    const float* hrow = embs + r * 128;
#pragma unroll 4
    for (int k = 0; k < 128; k++) {
        float hv = hrow[k];
        ull hp = pack2(hv, hv);
        const float* wr = W1s + k * 128;
#pragma unroll
        for (int i = 0; i < 4; i++) {
            ulonglong2 wv = *(const ulonglong2*)(wr + 4 * u + 32 * i);
            acc[2 * i]     = ffma2(hp, wv.x, acc[2 * i]);
            acc[2 * i + 1] = ffma2(hp, wv.y, acc[2 * i + 1]);
        }
    }
    float* outp = g_h + (rowBase + r) * 128;
#pragma unroll
    for (int i = 0; i < 4; i++) {
        float4 o;
        o.x = gelu_exact(lo2(acc[2 * i]));
        o.y = gelu_exact(hi2(acc[2 * i]));
        o.z = gelu_exact(lo2(acc[2 * i + 1]));
        o.w = gelu_exact(hi2(acc[2 * i + 1]));
        *(float4*)(outp + 4 * u + 32 * i) = o;
    }
}

// ---------------------------------------------------------------------------
// TP shuffle-reduction: acc (8 ull = 16 fp32 cols of this thread),
// coefficient vector c16[u_tp], reduce over u_tp, lanes with usub==0 write
// the 4 w' values of their group into r16.
// Thread col mapping: col_local = 4u + 64i + j  ->  u_tp = 4i + (u>>2),
// w' = (u&3)*4 + j.  Reduction over u_tp = in-thread over i + xor-shfl 4,8.
// ---------------------------------------------------------------------------
__device__ __forceinline__ void tp_reduce(const ull* acc, const float* c16,
                                          float* r16, int usub, int wq, bool add) {
    float p0 = 0.f, p1 = 0.f, p2 = 0.f, p3 = 0.f;
#pragma unroll
    for (int i = 0; i < 4; i++) {
        float cu = c16[4 * i + usub];
        p0 = fmaf(cu, lo2(acc[2 * i]), p0);
        p1 = fmaf(cu, hi2(acc[2 * i]), p1);
        p2 = fmaf(cu, lo2(acc[2 * i + 1]), p2);
        p3 = fmaf(cu, hi2(acc[2 * i + 1]), p3);
    }
    p0 += __shfl_xor_sync(0xffffffffu, p0, 4);
    p1 += __shfl_xor_sync(0xffffffffu, p1, 4);
    p2 += __shfl_xor_sync(0xffffffffu, p2, 4);
    p3 += __shfl_xor_sync(0xffffffffu, p3, 4);
    p0 += __shfl_xor_sync(0xffffffffu, p0, 8);
    p1 += __shfl_xor_sync(0xffffffffu, p1, 8);
    p2 += __shfl_xor_sync(0xffffffffu, p2, 8);
    p3 += __shfl_xor_sync(0xffffffffu, p3, 8);
    if (usub == 0) {
        float* d = r16 + wq * 4;
        if (add) { d[0] += p0; d[1] += p1; d[2] += p2; d[3] += p3; }
        else     { d[0]  = p0; d[1]  = p1; d[2]  = p2; d[3]  = p3; }
    }
}

// ---------------------------------------------------------------------------
// Kernel 2: fused GEMM2 (h @ W2 + b2) + tensor product + atomic scatter.
// Block: 64 edges, 256 threads. Loops the 4 weight "types" (256-col chunks),
// staging W2 in 32k x 256n smem tiles. Thread (u = tid&15, rg = tid>>4)
// computes 16 cols for 4 edges {rg, rg+16, rg+32, rg+48}.
// ---------------------------------------------------------------------------
__global__ void __launch_bounds__(256)
k_fused(const float* __restrict__ xfeat, const float* __restrict__ esh,
        const float* __restrict__ W2, const float* __restrict__ b2,
        const int* __restrict__ src, const int* __restrict__ dstp,
        float* __restrict__ out) {
    extern __shared__ float smem[];
    float* h_s  = smem;               // 64*128 = 8192
    float* w2s  = h_s + 8192;         // 32*256 = 8192
    float* c0s  = w2s + 8192;         // 64*16
    float* c1s  = c0s + 1024;
    float* c2s  = c1s + 1024;
    float* c3s  = c2s + 1024;         // 64*48 ([e][m][u])
    float* r0s  = c3s + 3072;         // 64*16
    float* r2s  = r0s + 1024;
    float* r3s  = r2s + 1024;         // 64*48 ([e][m][w'])
    float* sh1s = r3s + 3072;         // 64*4
    int*   dsts = (int*)(sh1s + 256); // 64

    int tid = threadIdx.x;
    int eBase = blockIdx.x * TE2;

    {   // stage h tile (coalesced)
        const float4* hv = (const float4*)(g_h + (size_t)eBase * 128);
        float4* hsv = (float4*)h_s;
#pragma unroll
        for (int it = 0; it < 8; it++) hsv[it * 256 + tid] = hv[it * 256 + tid];
    }
    {   // per-edge TP coefficients: 4 threads/edge, 4 u each
        int e  = tid >> 2;
        int ge = eBase + e;
        int u0 = (tid & 3) * 4;
        int si = __ldg(src + ge);
        const float* x   = xfeat + (size_t)si * 64;
        const float* shp = esh + (size_t)ge * 4;
        float sh0 = __ldg(shp + 0);
        float s1x = __ldg(shp + 1), s1y = __ldg(shp + 2), s1z = __ldg(shp + 3);
#pragma unroll
        for (int du = 0; du < 4; du++) {
            int u = u0 + du;
            float s  = __ldg(x + u);
            float v0 = __ldg(x + 16 + 3 * u);
            float v1 = __ldg(x + 17 + 3 * u);
            float v2 = __ldg(x + 18 + 3 * u);
            c0s[e * 16 + u] = sh0 * s;
            c1s[e * 16 + u] = INV_SQRT3 * (v0 * s1x + v1 * s1y + v2 * s1z);
            c2s[e * 16 + u] = s;
            c3s[e * 48 + 0 * 16 + u] = sh0 * v0;
            c3s[e * 48 + 1 * 16 + u] = sh0 * v1;
            c3s[e * 48 + 2 * 16 + u] = sh0 * v2;
        }
        if ((tid & 3) == 0) {
            dsts[e] = __ldg(dstp + ge);
            sh1s[e * 4 + 0] = s1x; sh1s[e * 4 + 1] = s1y; sh1s[e * 4 + 2] = s1z;
        }
    }

    int u    = tid & 15;
    int rg   = tid >> 4;
    int usub = u >> 2;
    int wq   = u & 3;
    const float* hrow0 = h_s + (rg +  0) * 128;
    const float* hrow1 = h_s + (rg + 16) * 128;
    const float* hrow2 = h_s + (rg + 32) * 128;
    const float* hrow3 = h_s + (rg + 48) * 128;

#pragma unroll
    for (int t = 0; t < 4; t++) {
        ull acc[4][8];
#pragma unroll
        for (int i = 0; i < 4; i++) {   // init with bias (same for all edges)
            const float* bp = b2 + t * 256 + (u + 16 * i) * 4;
            ull blo = pack2(__ldg(bp + 0), __ldg(bp + 1));
            ull bhi = pack2(__ldg(bp + 2), __ldg(bp + 3));
#pragma unroll
            for (int s = 0; s < 4; s++) { acc[s][2 * i] = blo; acc[s][2 * i + 1] = bhi; }
        }
        for (int k0 = 0; k0 < 128; k0 += 32) {
            __syncthreads();
            {   // stage W2[k0..k0+32, t*256..t*256+256]
                const float4* wv = (const float4*)(W2 + (size_t)k0 * 1024 + t * 256);
                float4* wsv = (float4*)w2s;
#pragma unroll
                for (int it = 0; it < 8; it++) {
                    int idx = it * 256 + tid;
                    int row = idx >> 6;
                    int c4  = idx & 63;
                    wsv[row * 64 + c4] = wv[row * 256 + c4];
                }
            }
            __syncthreads();
#pragma unroll 4
            for (int kk = 0; kk < 32; kk++) {
                float h0 = hrow0[k0 + kk], h1 = hrow1[k0 + kk];
                float h2 = hrow2[k0 + kk], h3 = hrow3[k0 + kk];
                ull hp0 = pack2(h0, h0), hp1 = pack2(h1, h1);
                ull hp2 = pack2(h2, h2), hp3 = pack2(h3, h3);
                const float* wr = w2s + kk * 256;
#pragma unroll
                for (int i = 0; i < 4; i++) {
                    ulonglong2 wv = *(const ulonglong2*)(wr + (u + 16 * i) * 4);
                    acc[0][2 * i]     = ffma2(hp0, wv.x, acc[0][2 * i]);
                    acc[0][2 * i + 1] = ffma2(hp0, wv.y, acc[0][2 * i + 1]);
                    acc[1][2 * i]     = ffma2(hp1, wv.x, acc[1][2 * i]);
                    acc[1][2 * i + 1] = ffma2(hp1, wv.y, acc[1][2 * i + 1]);
                    acc[2][2 * i]     = ffma2(hp2, wv.x, acc[2][2 * i]);
                    acc[2][2 * i + 1] = ffma2(hp2, wv.y, acc[2][2 * i + 1]);
                    acc[3][2 * i]     = ffma2(hp3, wv.x, acc[3][2 * i]);
                    acc[3][2 * i + 1] = ffma2(hp3, wv.y, acc[3][2 * i + 1]);
                }
            }
        }
        // TP contraction of this 256-col chunk (uniform control flow per warp)
        if (t == 0) {
#pragma unroll
            for (int s = 0; s < 4; s++) {
                int e = rg + 16 * s;
                tp_reduce(acc[s], c0s + e * 16, r0s + e * 16, usub, wq, false);
            }
        } else if (t == 1) {
#pragma unroll
            for (int s = 0; s < 4; s++) {
                int e = rg + 16 * s;
                tp_reduce(acc[s], c1s + e * 16, r0s + e * 16, usub, wq, true);
            }
        } else if (t == 2) {
#pragma unroll
            for (int s = 0; s < 4; s++) {
                int e = rg + 16 * s;
                tp_reduce(acc[s], c2s + e * 16, r2s + e * 16, usub, wq, false);
            }
        } else {
#pragma unroll
            for (int m = 0; m < 3; m++) {
#pragma unroll
                for (int s = 0; s < 4; s++) {
                    int e = rg + 16 * s;
                    tp_reduce(acc[s], c3s + e * 48 + m * 16, r3s + e * 48 + m * 16,
                              usub, wq, false);
                }
            }
        }
    }
    __syncthreads();

    {   // combine + atomic scatter: 16 outputs per thread
        int e  = tid >> 2;
        int jb = (tid & 3) * 16;
        int d  = dsts[e];
        float* op = out + (size_t)d * 64;
        if (jb == 0) {
#pragma unroll
            for (int j = 0; j < 16; j++)
                atomicAdd(op + j, ALPHA * r0s[e * 16 + j]);
            atomicAdd(&g_cnt[d], 1.0f);
        } else {
#pragma unroll
            for (int jj = 0; jj < 16; jj++) {
                int q  = jb - 16 + jj;     // 0..47
                int wp = q / 3;
                int m  = q - 3 * wp;
                float val = ALPHA * (sh1s[e * 4 + m] * r2s[e * 16 + wp] +
                                     r3s[e * 48 + m * 16 + wp]);
                atomicAdd(op + 16 + q, val);
            }
        }
    }
}

// ---------------------------------------------------------------------------
// Kernel 3: segment mean normalization
// ---------------------------------------------------------------------------
__global__ void k_norm(float* __restrict__ out) {
    int i = blockIdx.x * blockDim.x + threadIdx.x;
    if (i < NNODES * 64) {
        float c = g_cnt[i >> 6];
        out[i] = out[i] / fmaxf(c, 1.0f);
    }
}

// ---------------------------------------------------------------------------
extern "C" void kernel_launch(void* const* d_in, const int* in_sizes, int n_in,
                              void* d_out, int out_size) {
    const float* xfeat = (const float*)d_in[0];  // src_features (10000,64)
    const float* eshv  = (const float*)d_in[1];  // edge_sh (160000,4)
    const float* emb   = (const float*)d_in[2];  // edge_emb (160000,128)
    const float* W1    = (const float*)d_in[3];  // (128,128)
    const float* b1    = (const float*)d_in[4];  // (128,)
    const float* W2    = (const float*)d_in[5];  // (128,1024)
    const float* b2    = (const float*)d_in[6];  // (1024,)
    const int*   src   = (const int*)d_in[7];    // (160000,)
    const int*   dstp  = (const int*)d_in[8];    // (160000,)
    float* out = (float*)d_out;                  // (10000,64) f32

    const int SMEM1 = (128 * 128 + TE1 * 128) * 4;                     // 81920
    const int SMEM2 = (8192 + 8192 + 1024 * 3 + 3072 + 1024 * 2 + 3072 + 256) * 4
                      + 64 * 4;                                        // ~109.3 KB
    cudaFuncSetAttribute(k_mlp1, cudaFuncAttributeMaxDynamicSharedMemorySize, SMEM1);
    cudaFuncSetAttribute(k_fused, cudaFuncAttributeMaxDynamicSharedMemorySize, SMEM2);

    k_zero<<<(NNODES * 64 + 255) / 256, 256>>>(out);
    k_mlp1<<<E_TOTAL / TE1, 256, SMEM1>>>(emb, W1, b1);
    k_fused<<<E_TOTAL / TE2, 256, SMEM2>>>(xfeat, eshv, W2, b2, src, dstp, out);
    k_norm<<<(NNODES * 64 + 255) / 256, 256>>>(out);
}

// round 5
// speedup vs baseline: 3.6917x; 3.6917x over previous
#include <cuda_runtime.h>
#include <math.h>
#include <cstdint>

#define E_TOTAL 160000
#define NNODES  10000
#define EPB     128
#define INV_SQRT3 0.5773502691896258f
#define ALPHA     0.17677669529663687f

// ---- smem float offsets ----
#define HS_OFF   0        // [128][132] emb->h tile
#define WS_OFF   16896    // [2][8192] W fragment staging (W1F whole / W2F chunks)
#define CS0_OFF  33280    // [128][17]
#define CS1_OFF  35456
#define CS2_OFF  37632
#define VS_OFF   39808    // [128][49]  (3u+m)
#define SH1_OFF  46080    // [128][3]
#define B1_OFF   46464    // 128
#define B2_OFF   46592    // 1024
#define DST_OFF  47616    // 128 int
#define TOTF     47744
#define SMEM_BYTES (TOTF * 4)

// fragment-ordered tf32 weights: [.][nt][kt][lane][2]
__device__ float g_W1F[16384];        // [2 halves][8][16][32][2]
__device__ float g_W2F[16 * 8192];    // [16 chunks][8][16][32][2]
__device__ float g_cnt[NNODES];

__device__ __forceinline__ float to_tf32(float x) {
    unsigned u; asm("cvt.rna.tf32.f32 %0, %1;" : "=r"(u) : "f"(x));
    return __uint_as_float(u);
}
__device__ __forceinline__ float gelu_exact(float x) {
    return 0.5f * x * (1.0f + erff(x * 0.7071067811865476f));
}
__device__ __forceinline__ void red2(float* p, float a, float b) {
    asm volatile("red.global.add.v2.f32 [%0], {%1, %2};"
                 :: "l"(p), "f"(a), "f"(b) : "memory");
}
__device__ __forceinline__ void mma8(float* c, const unsigned* a, float2 b) {
    unsigned b0 = __float_as_uint(b.x), b1 = __float_as_uint(b.y);
    asm("mma.sync.aligned.m16n8k8.row.col.f32.tf32.tf32.f32 "
        "{%0,%1,%2,%3}, {%4,%5,%6,%7}, {%8,%9}, {%0,%1,%2,%3};"
        : "+f"(c[0]), "+f"(c[1]), "+f"(c[2]), "+f"(c[3])
        : "r"(a[0]), "r"(a[1]), "r"(a[2]), "r"(a[3]), "r"(b0), "r"(b1));
}

// ---------------- prep: tf32 weights in mma fragment order ----------------
__global__ void k_prep(const float* __restrict__ W1, const float* __restrict__ W2) {
    int i = blockIdx.x * 256 + threadIdx.x;
    if (i < 16384) {
        int j = i & 1, lane = (i >> 1) & 31, kt = (i >> 6) & 15;
        int nt = (i >> 10) & 7, h = i >> 13;
        int q = lane & 3, g = lane >> 2;
        int k = kt * 8 + q + 4 * j, n = h * 64 + nt * 8 + g;
        g_W1F[i] = to_tf32(W1[k * 128 + n]);
    } else if (i < 16384 + 131072) {
        int ii = i - 16384;
        int j = ii & 1, lane = (ii >> 1) & 31, kt = (ii >> 6) & 15;
        int nt = (ii >> 10) & 7, c = ii >> 13;
        int q = lane & 3, g = lane >> 2;
        int k = kt * 8 + q + 4 * j, col = c * 64 + nt * 8 + g;
        g_W2F[ii] = to_tf32(W2[k * 1024 + col]);
    }
}

__global__ void k_zero(float* __restrict__ out) {
    int i = blockIdx.x * blockDim.x + threadIdx.x;
    if (i < NNODES * 64) out[i] = 0.0f;
    if (i < NNODES) g_cnt[i] = 0.0f;
}
__global__ void k_norm(float* __restrict__ out) {
    int i = blockIdx.x * blockDim.x + threadIdx.x;
    if (i < NNODES * 64) out[i] = out[i] / fmaxf(g_cnt[i >> 6], 1.0f);
}

// ---------------- fused kernel ----------------
__global__ void __launch_bounds__(256, 1)
k_fused(const float* __restrict__ xfeat, const float* __restrict__ esh,
        const float* __restrict__ emb, const float* __restrict__ b1,
        const float* __restrict__ b2, const int* __restrict__ src,
        const int* __restrict__ dstp, float* __restrict__ out) {
    extern __shared__ float sm[];
    const int tid = threadIdx.x, wid = tid >> 5, lane = tid & 31;
    const int qq = lane & 3, gg = lane >> 2;
    const int eBase = blockIdx.x * EPB;
    const int r0 = 16 * wid + gg, r1 = r0 + 8;

    // ---- stage emb tile (tf32) into hs, W1F into ws, biases ----
#pragma unroll
    for (int it = 0; it < 16; it++) {
        int qi = it * 256 + tid;
        int rr = qi >> 5, c4 = qi & 31;
        float4 v = *(const float4*)(emb + (size_t)(eBase + rr) * 128 + 4 * c4);
        v.x = to_tf32(v.x); v.y = to_tf32(v.y); v.z = to_tf32(v.z); v.w = to_tf32(v.w);
        *(float4*)(sm + rr * 132 + 4 * c4) = v;
    }
    {
        const float4* s4 = (const float4*)g_W1F;
        float4* d4 = (float4*)(sm + WS_OFF);
#pragma unroll
        for (int it = 0; it < 16; it++) d4[it * 256 + tid] = s4[it * 256 + tid];
    }
    if (tid < 128) sm[B1_OFF + tid] = b1[tid];
    ((float4*)(sm + B2_OFF))[tid] = ((const float4*)b2)[tid];

    // ---- per-edge TP coefficients (2 threads / edge) ----
    {
        int e = tid >> 1, ge = eBase + e, u0 = (tid & 1) * 8;
        int si = __ldg(src + ge);
        const float* x = xfeat + (size_t)si * 64;
        float4 shv = *(const float4*)(esh + (size_t)ge * 4);
        float sh0 = shv.x, s1x = shv.y, s1y = shv.z, s1z = shv.w;
        float4 aq = *(const float4*)(x + u0), bq = *(const float4*)(x + u0 + 4);
        float sv[8] = {aq.x, aq.y, aq.z, aq.w, bq.x, bq.y, bq.z, bq.w};
        float vv[24];
#pragma unroll
        for (int p = 0; p < 6; p++) {
            float4 t = *(const float4*)(x + 16 + 3 * u0 + 4 * p);
            vv[4*p] = t.x; vv[4*p+1] = t.y; vv[4*p+2] = t.z; vv[4*p+3] = t.w;
        }
#pragma unroll
        for (int du = 0; du < 8; du++) {
            int u = u0 + du;
            float s = sv[du], v0 = vv[3*du], v1 = vv[3*du+1], v2 = vv[3*du+2];
            sm[CS0_OFF + e * 17 + u] = sh0 * s;
            sm[CS1_OFF + e * 17 + u] = INV_SQRT3 * (v0 * s1x + v1 * s1y + v2 * s1z);
            sm[CS2_OFF + e * 17 + u] = s;
            sm[VS_OFF + e * 49 + 3 * u + 0] = sh0 * v0;
            sm[VS_OFF + e * 49 + 3 * u + 1] = sh0 * v1;
            sm[VS_OFF + e * 49 + 3 * u + 2] = sh0 * v2;
        }
        if ((tid & 1) == 0) {
            sm[SH1_OFF + e * 3 + 0] = s1x;
            sm[SH1_OFF + e * 3 + 1] = s1y;
            sm[SH1_OFF + e * 3 + 2] = s1z;
            ((int*)(sm + DST_OFF))[e] = __ldg(dstp + ge);
        }
    }
    __syncthreads();

    // ---- A fragments (emb rows of this warp) ----
    unsigned a[16][4];
#pragma unroll
    for (int kt = 0; kt < 16; kt++) {
        a[kt][0] = __float_as_uint(sm[r0 * 132 + kt * 8 + qq]);
        a[kt][1] = __float_as_uint(sm[r1 * 132 + kt * 8 + qq]);
        a[kt][2] = __float_as_uint(sm[r0 * 132 + kt * 8 + qq + 4]);
        a[kt][3] = __float_as_uint(sm[r1 * 132 + kt * 8 + qq + 4]);
    }

    // ---- GEMM1: two 64-col halves, gelu epilogue writes h over emb ----
#pragma unroll
    for (int h = 0; h < 2; h++) {
        float acc[8][4];
#pragma unroll
        for (int nt = 0; nt < 8; nt++)
#pragma unroll
            for (int j = 0; j < 4; j++) acc[nt][j] = 0.0f;
#pragma unroll
        for (int kt = 0; kt < 16; kt++)
#pragma unroll
            for (int nt = 0; nt < 8; nt++) {
                float2 bv = *(const float2*)(sm + WS_OFF + h * 8192 +
                                             ((nt * 16 + kt) * 32 + lane) * 2);
                mma8(acc[nt], a[kt], bv);
            }
#pragma unroll
        for (int nt = 0; nt < 8; nt++) {
            int col = h * 64 + nt * 8 + 2 * qq;
            float2 bb = *(const float2*)(sm + B1_OFF + col);
            float2 h0, h1;
            h0.x = to_tf32(gelu_exact(acc[nt][0] + bb.x));
            h0.y = to_tf32(gelu_exact(acc[nt][1] + bb.y));
            h1.x = to_tf32(gelu_exact(acc[nt][2] + bb.x));
            h1.y = to_tf32(gelu_exact(acc[nt][3] + bb.y));
            *(float2*)(sm + r0 * 132 + col) = h0;
            *(float2*)(sm + r1 * 132 + col) = h1;
        }
    }
    __syncwarp();
    // reload A fragments = h
#pragma unroll
    for (int kt = 0; kt < 16; kt++) {
        a[kt][0] = __float_as_uint(sm[r0 * 132 + kt * 8 + qq]);
        a[kt][1] = __float_as_uint(sm[r1 * 132 + kt * 8 + qq]);
        a[kt][2] = __float_as_uint(sm[r0 * 132 + kt * 8 + qq + 4]);
        a[kt][3] = __float_as_uint(sm[r1 * 132 + kt * 8 + qq + 4]);
    }
    __syncthreads();   // all warps done with W1F in ws

    // stage W2 chunk 0 into buf 0
    {
        const float4* s4 = (const float4*)g_W2F;
        float4* d4 = (float4*)(sm + WS_OFF);
#pragma unroll
        for (int it = 0; it < 8; it++) d4[it * 256 + tid] = s4[it * 256 + tid];
    }
    __syncthreads();

    float r0a[2][4], r2a[2][4], r3a[2][4][3];
#pragma unroll
    for (int ei = 0; ei < 2; ei++)
#pragma unroll
        for (int s = 0; s < 4; s++) {
            r0a[ei][s] = 0.0f; r2a[ei][s] = 0.0f;
            r3a[ei][s][0] = 0.0f; r3a[ei][s][1] = 0.0f; r3a[ei][s][2] = 0.0f;
        }

#pragma unroll 1
    for (int c = 0; c < 16; c++) {
        if (c < 15) {   // prefetch next chunk into other buffer
            const float4* s4 = (const float4*)(g_W2F + (c + 1) * 8192);
            float4* d4 = (float4*)(sm + WS_OFF + ((c + 1) & 1) * 8192);
#pragma unroll
            for (int it = 0; it < 8; it++) d4[it * 256 + tid] = s4[it * 256 + tid];
        }
        const float* wb = sm + WS_OFF + (c & 1) * 8192;
        float acc[8][4];
#pragma unroll
        for (int nt = 0; nt < 8; nt++)
#pragma unroll
            for (int j = 0; j < 4; j++) acc[nt][j] = 0.0f;
#pragma unroll
        for (int kt = 0; kt < 16; kt++)
#pragma unroll
            for (int nt = 0; nt < 8; nt++) {
                float2 bv = *(const float2*)(wb + ((nt * 16 + kt) * 32 + lane) * 2);
                mma8(acc[nt], a[kt], bv);
            }

        const int t = c >> 2, g4 = c & 3;
        if (t <= 1) {
            const float* cb = sm + (t == 0 ? CS0_OFF : CS1_OFF);
            float cc0[4], cc1[4];
#pragma unroll
            for (int ul = 0; ul < 4; ul++) {
                cc0[ul] = cb[r0 * 17 + 4 * g4 + ul];
                cc1[ul] = cb[r1 * 17 + 4 * g4 + ul];
            }
#pragma unroll
            for (int nt = 0; nt < 8; nt++) {
                int ul = nt >> 1, p = nt & 1;
                float2 bb = *(const float2*)(sm + B2_OFF + c * 64 + nt * 8 + 2 * qq);
                float d0 = acc[nt][0] + bb.x, d1 = acc[nt][1] + bb.y;
                float d2 = acc[nt][2] + bb.x, d3 = acc[nt][3] + bb.y;
                r0a[0][2*p]   = fmaf(cc0[ul], d0, r0a[0][2*p]);
                r0a[0][2*p+1] = fmaf(cc0[ul], d1, r0a[0][2*p+1]);
                r0a[1][2*p]   = fmaf(cc1[ul], d2, r0a[1][2*p]);
                r0a[1][2*p+1] = fmaf(cc1[ul], d3, r0a[1][2*p+1]);
            }
            if (c == 7) {
                int dn0 = ((int*)(sm + DST_OFF))[r0];
                int dn1 = ((int*)(sm + DST_OFF))[r1];
                float* op0 = out + (size_t)dn0 * 64;
                float* op1 = out + (size_t)dn1 * 64;
                red2(op0 + 2*qq,     ALPHA * r0a[0][0], ALPHA * r0a[0][1]);
                red2(op0 + 2*qq + 8, ALPHA * r0a[0][2], ALPHA * r0a[0][3]);
                red2(op1 + 2*qq,     ALPHA * r0a[1][0], ALPHA * r0a[1][1]);
                red2(op1 + 2*qq + 8, ALPHA * r0a[1][2], ALPHA * r0a[1][3]);
                if (qq == 0) {
                    atomicAdd(&g_cnt[dn0], 1.0f);
                    atomicAdd(&g_cnt[dn1], 1.0f);
                }
            }
        } else if (t == 2) {
            float cc0[4], cc1[4];
#pragma unroll
            for (int ul = 0; ul < 4; ul++) {
                cc0[ul] = sm[CS2_OFF + r0 * 17 + 4 * g4 + ul];
                cc1[ul] = sm[CS2_OFF + r1 * 17 + 4 * g4 + ul];
            }
#pragma unroll
            for (int nt = 0; nt < 8; nt++) {
                int ul = nt >> 1, p = nt & 1;
                float2 bb = *(const float2*)(sm + B2_OFF + c * 64 + nt * 8 + 2 * qq);
                float d0 = acc[nt][0] + bb.x, d1 = acc[nt][1] + bb.y;
                float d2 = acc[nt][2] + bb.x, d3 = acc[nt][3] + bb.y;
                r2a[0][2*p]   = fmaf(cc0[ul], d0, r2a[0][2*p]);
                r2a[0][2*p+1] = fmaf(cc0[ul], d1, r2a[0][2*p+1]);
                r2a[1][2*p]   = fmaf(cc1[ul], d2, r2a[1][2*p]);
                r2a[1][2*p+1] = fmaf(cc1[ul], d3, r2a[1][2*p+1]);
            }
        } else {
            float v0[4][3], v1[4][3];
#pragma unroll
            for (int ul = 0; ul < 4; ul++)
#pragma unroll
                for (int m = 0; m < 3; m++) {
                    v0[ul][m] = sm[VS_OFF + r0 * 49 + 3 * (4 * g4 + ul) + m];
                    v1[ul][m] = sm[VS_OFF + r1 * 49 + 3 * (4 * g4 + ul) + m];
                }
#pragma unroll
            for (int nt = 0; nt < 8; nt++) {
                int ul = nt >> 1, p = nt & 1;
                float2 bb = *(const float2*)(sm + B2_OFF + c * 64 + nt * 8 + 2 * qq);
                float d0 = acc[nt][0] + bb.x, d1 = acc[nt][1] + bb.y;
                float d2 = acc[nt][2] + bb.x, d3 = acc[nt][3] + bb.y;
#pragma unroll
                for (int m = 0; m < 3; m++) {
                    r3a[0][2*p][m]   = fmaf(v0[ul][m], d0, r3a[0][2*p][m]);
                    r3a[0][2*p+1][m] = fmaf(v0[ul][m], d1, r3a[0][2*p+1][m]);
                    r3a[1][2*p][m]   = fmaf(v1[ul][m], d2, r3a[1][2*p][m]);
                    r3a[1][2*p+1][m] = fmaf(v1[ul][m], d3, r3a[1][2*p+1][m]);
                }
            }
            if (c == 15) {
                int dns[2] = {((int*)(sm + DST_OFF))[r0], ((int*)(sm + DST_OFF))[r1]};
                int ers[2] = {r0, r1};
#pragma unroll
                for (int ei = 0; ei < 2; ei++) {
                    float s1m[3];
#pragma unroll
                    for (int m = 0; m < 3; m++) s1m[m] = sm[SH1_OFF + ers[ei] * 3 + m];
                    float* op = out + (size_t)dns[ei] * 64 + 16;
                    float va[4][3];
#pragma unroll
                    for (int s = 0; s < 4; s++)
#pragma unroll
                        for (int m = 0; m < 3; m++)
                            va[s][m] = ALPHA * fmaf(s1m[m], r2a[ei][s], r3a[ei][s][m]);
                    // slots 0,1 -> w' = 2q, 2q+1 : out idx 16+6q .. +5
                    red2(op + 6*qq + 0, va[0][0], va[0][1]);
                    red2(op + 6*qq + 2, va[0][2], va[1][0]);
                    red2(op + 6*qq + 4, va[1][1], va[1][2]);
                    // slots 2,3 -> w' = 2q+8, 2q+9 : base +24
                    red2(op + 6*qq + 24, va[2][0], va[2][1]);
                    red2(op + 6*qq + 26, va[2][2], va[3][0]);
                    red2(op + 6*qq + 28, va[3][1], va[3][2]);
                }
            }
        }
        __syncthreads();
    }
}

// ---------------------------------------------------------------------------
extern "C" void kernel_launch(void* const* d_in, const int* in_sizes, int n_in,
                              void* d_out, int out_size) {
    const float* xfeat = (const float*)d_in[0];
    const float* eshv  = (const float*)d_in[1];
    const float* emb   = (const float*)d_in[2];
    const float* W1    = (const float*)d_in[3];
    const float* b1    = (const float*)d_in[4];
    const float* W2    = (const float*)d_in[5];
    const float* b2    = (const float*)d_in[6];
    const int*   src   = (const int*)d_in[7];
    const int*   dstp  = (const int*)d_in[8];
    float* out = (float*)d_out;

    cudaFuncSetAttribute(k_fused, cudaFuncAttributeMaxDynamicSharedMemorySize, SMEM_BYTES);

    k_zero<<<(NNODES * 64 + 255) / 256, 256>>>(out);
    k_prep<<<(16384 + 131072 + 255) / 256, 256>>>(W1, W2);
    k_fused<<<E_TOTAL / EPB, 256, SMEM_BYTES>>>(xfeat, eshv, emb, b1, b2, src, dstp, out);
    k_norm<<<(NNODES * 64 + 255) / 256, 256>>>(out);
}

// round 6
// speedup vs baseline: 6.3549x; 1.7214x over previous
#include <cuda_runtime.h>
#include <cuda_fp16.h>
#include <math.h>
#include <cstdint>

#define E_TOTAL 160000
#define NNODES  10000
#define EPB     128
#define INV_SQRT3 0.5773502691896258f
#define ALPHA     0.17677669529663687f

// ---- smem float offsets ----
// HS: 128 rows x 136 halves (h tile, fp16)        [0, 8704) floats
#define WS_OFF   8704     // 2 x 16KB W fragment buffers (fp16)
#define CS0_OFF  16896    // [128][17] f32
#define CS1_OFF  19072
#define CS2_OFF  21248
#define VS_OFF   23424    // [128][49]
#define SH1_OFF  29696    // [128][3]
#define B1_OFF   30080    // 128
#define B2_OFF   30208    // 1024
#define DST_OFF  31232    // 128 int
#define TOTF     31360
#define SMEM_BYTES (TOTF * 4)

// fragment-ordered fp16 weights: [.][nt][kt(8)][lane][pair][hh]
__device__ __align__(16) __half g_W1F[16384];        // 32KB
__device__ __align__(16) __half g_W2F[16 * 8192];    // 16 chunks x 16KB
__device__ float g_cnt[NNODES];

__device__ __forceinline__ float gelu_exact(float x) {
    return 0.5f * x * (1.0f + erff(x * 0.7071067811865476f));
}
__device__ __forceinline__ void red2(float* p, float a, float b) {
    asm volatile("red.global.add.v2.f32 [%0], {%1, %2};"
                 :: "l"(p), "f"(a), "f"(b) : "memory");
}
__device__ __forceinline__ void mma16(float* c, const unsigned* a,
                                      unsigned b0, unsigned b1) {
    asm("mma.sync.aligned.m16n8k16.row.col.f32.f16.f16.f32 "
        "{%0,%1,%2,%3}, {%4,%5,%6,%7}, {%8,%9}, {%0,%1,%2,%3};"
        : "+f"(c[0]), "+f"(c[1]), "+f"(c[2]), "+f"(c[3])
        : "r"(a[0]), "r"(a[1]), "r"(a[2]), "r"(a[3]), "r"(b0), "r"(b1));
}
__device__ __forceinline__ void cpasync16(uint32_t s, const void* g) {
    asm volatile("cp.async.cg.shared.global [%0], [%1], 16;" :: "r"(s), "l"(g));
}
__device__ __forceinline__ void cpcommit() {
    asm volatile("cp.async.commit_group;" ::: "memory");
}
__device__ __forceinline__ void cpwait0() {
    asm volatile("cp.async.wait_group 0;" ::: "memory");
}

// ---------------- prep: fp16 weights in m16n8k16 fragment order ----------------
// idx = ((((blk*8+nt)*8+kt)*32+lane)*2+pair)*2+hh ; k=kt*16+pair*8+2q+hh
__global__ void k_prep(const float* __restrict__ W1, const float* __restrict__ W2) {
    int i = blockIdx.x * 256 + threadIdx.x;
    if (i < 16384) {
        int hh = i & 1, pair = (i >> 1) & 1, lane = (i >> 2) & 31;
        int kt = (i >> 7) & 7, nt = (i >> 10) & 7, h = (i >> 13) & 1;
        int q = lane & 3, g = lane >> 2;
        int k = kt * 16 + pair * 8 + 2 * q + hh, n = h * 64 + nt * 8 + g;
        g_W1F[i] = __float2half_rn(W1[k * 128 + n]);
    } else if (i < 16384 + 131072) {
        int j = i - 16384;
        int hh = j & 1, pair = (j >> 1) & 1, lane = (j >> 2) & 31;
        int kt = (j >> 7) & 7, nt = (j >> 10) & 7, c = (j >> 13) & 15;
        int q = lane & 3, g = lane >> 2;
        int k = kt * 16 + pair * 8 + 2 * q + hh, col = c * 64 + nt * 8 + g;
        g_W2F[j] = __float2half_rn(W2[k * 1024 + col]);
    }
}

__global__ void k_zero(float* __restrict__ out) {
    int i = blockIdx.x * blockDim.x + threadIdx.x;
    if (i < NNODES * 64) out[i] = 0.0f;
    if (i < NNODES) g_cnt[i] = 0.0f;
}
__global__ void k_norm(float* __restrict__ out) {
    int i = blockIdx.x * blockDim.x + threadIdx.x;
    if (i < NNODES * 64) out[i] = out[i] / fmaxf(g_cnt[i >> 6], 1.0f);
}

// ---------------- fused kernel ----------------
__global__ void __launch_bounds__(256, 1)
k_fused(const float* __restrict__ xfeat, const float* __restrict__ esh,
        const float* __restrict__ emb, const float* __restrict__ b1,
        const float* __restrict__ b2, const int* __restrict__ src,
        const int* __restrict__ dstp, float* __restrict__ out) {
    extern __shared__ float sm[];
    __half* hs = (__half*)sm;                    // 128 x 136 halves (272B rows)
    char* wsc = (char*)(sm + WS_OFF);
    const uint32_t wsb = (uint32_t)__cvta_generic_to_shared(wsc);
    const int tid = threadIdx.x, wid = tid >> 5, lane = tid & 31;
    const int qq = lane & 3, gg = lane >> 2;
    const int eBase = blockIdx.x * EPB;
    const int r0 = 16 * wid + gg, r1 = r0 + 8;

    // ---- stage emb tile as fp16 (stride 136 halves) ----
#pragma unroll
    for (int it = 0; it < 16; it++) {
        int qi = it * 256 + tid;
        int rr = qi >> 5, c4 = qi & 31;
        float4 v = *(const float4*)(emb + (size_t)(eBase + rr) * 128 + 4 * c4);
        __half2 p0 = __floats2half2_rn(v.x, v.y);
        __half2 p1 = __floats2half2_rn(v.z, v.w);
        uint2 pk = {*(unsigned*)&p0, *(unsigned*)&p1};
        *(uint2*)((char*)hs + rr * 272 + 8 * c4) = pk;
    }
    // ---- stage W1F (32KB) via cp.async ----
#pragma unroll
    for (int it = 0; it < 8; it++)
        cpasync16(wsb + (it * 256 + tid) * 16, (const char*)g_W1F + (it * 256 + tid) * 16);
    cpcommit();
    // biases
    if (tid < 128) sm[B1_OFF + tid] = b1[tid];
    ((float4*)(sm + B2_OFF))[tid] = ((const float4*)b2)[tid];

    // ---- per-edge TP coefficients (2 threads / edge) ----
    {
        int e = tid >> 1, ge = eBase + e, u0 = (tid & 1) * 8;
        int si = __ldg(src + ge);
        const float* x = xfeat + (size_t)si * 64;
        float4 shv = *(const float4*)(esh + (size_t)ge * 4);
        float sh0 = shv.x, s1x = shv.y, s1y = shv.z, s1z = shv.w;
        float4 aq = *(const float4*)(x + u0), bq = *(const float4*)(x + u0 + 4);
        float sv[8] = {aq.x, aq.y, aq.z, aq.w, bq.x, bq.y, bq.z, bq.w};
        float vv[24];
#pragma unroll
        for (int p = 0; p < 6; p++) {
            float4 t = *(const float4*)(x + 16 + 3 * u0 + 4 * p);
            vv[4*p] = t.x; vv[4*p+1] = t.y; vv[4*p+2] = t.z; vv[4*p+3] = t.w;
        }
#pragma unroll
        for (int du = 0; du < 8; du++) {
            int u = u0 + du;
            float s = sv[du], v0 = vv[3*du], v1 = vv[3*du+1], v2 = vv[3*du+2];
            sm[CS0_OFF + e * 17 + u] = sh0 * s;
            sm[CS1_OFF + e * 17 + u] = INV_SQRT3 * (v0 * s1x + v1 * s1y + v2 * s1z);
            sm[CS2_OFF + e * 17 + u] = s;
            sm[VS_OFF + e * 49 + 3 * u + 0] = sh0 * v0;
            sm[VS_OFF + e * 49 + 3 * u + 1] = sh0 * v1;
            sm[VS_OFF + e * 49 + 3 * u + 2] = sh0 * v2;
        }
        if ((tid & 1) == 0) {
            sm[SH1_OFF + e * 3 + 0] = s1x;
            sm[SH1_OFF + e * 3 + 1] = s1y;
            sm[SH1_OFF + e * 3 + 2] = s1z;
            ((int*)(sm + DST_OFF))[e] = __ldg(dstp + ge);
        }
    }
    cpwait0();
    __syncthreads();

    // ---- A fragments (fp16 emb rows of this warp): 8 kt steps of k=16 ----
    unsigned a[8][4];
#pragma unroll
    for (int kt = 0; kt < 8; kt++) {
        a[kt][0] = *(const unsigned*)((char*)hs + r0 * 272 + kt * 32 + 4 * qq);
        a[kt][1] = *(const unsigned*)((char*)hs + r1 * 272 + kt * 32 + 4 * qq);
        a[kt][2] = *(const unsigned*)((char*)hs + r0 * 272 + kt * 32 + 4 * qq + 16);
        a[kt][3] = *(const unsigned*)((char*)hs + r1 * 272 + kt * 32 + 4 * qq + 16);
    }

    // ---- GEMM1: two 64-col halves, gelu epilogue writes h (fp16) over emb ----
#pragma unroll
    for (int h = 0; h < 2; h++) {
        float acc[8][4];
#pragma unroll
        for (int nt = 0; nt < 8; nt++)
#pragma unroll
            for (int j = 0; j < 4; j++) acc[nt][j] = 0.0f;
        const uint2* wb = (const uint2*)(wsc + h * 16384);
#pragma unroll
        for (int kt = 0; kt < 8; kt++)
#pragma unroll
            for (int nt = 0; nt < 8; nt++) {
                uint2 b = wb[(nt * 8 + kt) * 32 + lane];
                mma16(acc[nt], a[kt], b.x, b.y);
            }
#pragma unroll
        for (int nt = 0; nt < 8; nt++) {
            int col = h * 64 + nt * 8 + 2 * qq;
            float2 bb = *(const float2*)(sm + B1_OFF + col);
            __half2 h0 = __floats2half2_rn(gelu_exact(acc[nt][0] + bb.x),
                                           gelu_exact(acc[nt][1] + bb.y));
            __half2 h1 = __floats2half2_rn(gelu_exact(acc[nt][2] + bb.x),
                                           gelu_exact(acc[nt][3] + bb.y));
            *(__half2*)((char*)hs + r0 * 272 + col * 2) = h0;
            *(__half2*)((char*)hs + r1 * 272 + col * 2) = h1;
        }
    }
    __syncwarp();
    // reload A fragments = h
#pragma unroll
    for (int kt = 0; kt < 8; kt++) {
        a[kt][0] = *(const unsigned*)((char*)hs + r0 * 272 + kt * 32 + 4 * qq);
        a[kt][1] = *(const unsigned*)((char*)hs + r1 * 272 + kt * 32 + 4 * qq);
        a[kt][2] = *(const unsigned*)((char*)hs + r0 * 272 + kt * 32 + 4 * qq + 16);
        a[kt][3] = *(const unsigned*)((char*)hs + r1 * 272 + kt * 32 + 4 * qq + 16);
    }
    __syncthreads();   // all warps done with W1F

    // ---- stage W2 chunk 0 into buf 0 ----
#pragma unroll
    for (int it = 0; it < 4; it++)
        cpasync16(wsb + (it * 256 + tid) * 16, (const char*)g_W2F + (it * 256 + tid) * 16);
    cpcommit();
    cpwait0();
    __syncthreads();

    float r0a[2][4], r2a[2][4], r3a[2][4][3];
#pragma unroll
    for (int ei = 0; ei < 2; ei++)
#pragma unroll
        for (int s = 0; s < 4; s++) {
            r0a[ei][s] = 0.0f; r2a[ei][s] = 0.0f;
            r3a[ei][s][0] = 0.0f; r3a[ei][s][1] = 0.0f; r3a[ei][s][2] = 0.0f;
        }

#pragma unroll 1
    for (int c = 0; c < 16; c++) {
        if (c < 15) {   // prefetch next chunk into other buffer
#pragma unroll
            for (int it = 0; it < 4; it++)
                cpasync16(wsb + ((c + 1) & 1) * 16384 + (it * 256 + tid) * 16,
                          (const char*)g_W2F + (c + 1) * 16384 + (it * 256 + tid) * 16);
            cpcommit();
        }
        const uint2* wb = (const uint2*)(wsc + (c & 1) * 16384);
        float acc[8][4];
#pragma unroll
        for (int nt = 0; nt < 8; nt++)
#pragma unroll
            for (int j = 0; j < 4; j++) acc[nt][j] = 0.0f;
#pragma unroll
        for (int kt = 0; kt < 8; kt++)
#pragma unroll
            for (int nt = 0; nt < 8; nt++) {
                uint2 b = wb[(nt * 8 + kt) * 32 + lane];
                mma16(acc[nt], a[kt], b.x, b.y);
            }

        const int t = c >> 2, g4 = c & 3;
        if (t <= 1) {
            const float* cb = sm + (t == 0 ? CS0_OFF : CS1_OFF);
            float cc0[4], cc1[4];
#pragma unroll
            for (int ul = 0; ul < 4; ul++) {
                cc0[ul] = cb[r0 * 17 + 4 * g4 + ul];
                cc1[ul] = cb[r1 * 17 + 4 * g4 + ul];
            }
#pragma unroll
            for (int nt = 0; nt < 8; nt++) {
                int ul = nt >> 1, p = nt & 1;
                float2 bb = *(const float2*)(sm + B2_OFF + c * 64 + nt * 8 + 2 * qq);
                float d0 = acc[nt][0] + bb.x, d1 = acc[nt][1] + bb.y;
                float d2 = acc[nt][2] + bb.x, d3 = acc[nt][3] + bb.y;
                r0a[0][2*p]   = fmaf(cc0[ul], d0, r0a[0][2*p]);
                r0a[0][2*p+1] = fmaf(cc0[ul], d1, r0a[0][2*p+1]);
                r0a[1][2*p]   = fmaf(cc1[ul], d2, r0a[1][2*p]);
                r0a[1][2*p+1] = fmaf(cc1[ul], d3, r0a[1][2*p+1]);
            }
            if (c == 7) {
                int dn0 = ((int*)(sm + DST_OFF))[r0];
                int dn1 = ((int*)(sm + DST_OFF))[r1];
                float* op0 = out + (size_t)dn0 * 64;
                float* op1 = out + (size_t)dn1 * 64;
                red2(op0 + 2*qq,     ALPHA * r0a[0][0], ALPHA * r0a[0][1]);
                red2(op0 + 2*qq + 8, ALPHA * r0a[0][2], ALPHA * r0a[0][3]);
                red2(op1 + 2*qq,     ALPHA * r0a[1][0], ALPHA * r0a[1][1]);
                red2(op1 + 2*qq + 8, ALPHA * r0a[1][2], ALPHA * r0a[1][3]);
                if (qq == 0) {
                    atomicAdd(&g_cnt[dn0], 1.0f);
                    atomicAdd(&g_cnt[dn1], 1.0f);
                }
            }
        } else if (t == 2) {
            float cc0[4], cc1[4];
#pragma unroll
            for (int ul = 0; ul < 4; ul++) {
                cc0[ul] = sm[CS2_OFF + r0 * 17 + 4 * g4 + ul];
                cc1[ul] = sm[CS2_OFF + r1 * 17 + 4 * g4 + ul];
            }
#pragma unroll
            for (int nt = 0; nt < 8; nt++) {
                int ul = nt >> 1, p = nt & 1;
                float2 bb = *(const float2*)(sm + B2_OFF + c * 64 + nt * 8 + 2 * qq);
                float d0 = acc[nt][0] + bb.x, d1 = acc[nt][1] + bb.y;
                float d2 = acc[nt][2] + bb.x, d3 = acc[nt][3] + bb.y;
                r2a[0][2*p]   = fmaf(cc0[ul], d0, r2a[0][2*p]);
                r2a[0][2*p+1] = fmaf(cc0[ul], d1, r2a[0][2*p+1]);
                r2a[1][2*p]   = fmaf(cc1[ul], d2, r2a[1][2*p]);
                r2a[1][2*p+1] = fmaf(cc1[ul], d3, r2a[1][2*p+1]);
            }
        } else {
            float v0[4][3], v1[4][3];
#pragma unroll
            for (int ul = 0; ul < 4; ul++)
#pragma unroll
                for (int m = 0; m < 3; m++) {
                    v0[ul][m] = sm[VS_OFF + r0 * 49 + 3 * (4 * g4 + ul) + m];
                    v1[ul][m] = sm[VS_OFF + r1 * 49 + 3 * (4 * g4 + ul) + m];
                }
#pragma unroll
            for (int nt = 0; nt < 8; nt++) {
                int ul = nt >> 1, p = nt & 1;
                float2 bb = *(const float2*)(sm + B2_OFF + c * 64 + nt * 8 + 2 * qq);
                float d0 = acc[nt][0] + bb.x, d1 = acc[nt][1] + bb.y;
                float d2 = acc[nt][2] + bb.x, d3 = acc[nt][3] + bb.y;
#pragma unroll
                for (int m = 0; m < 3; m++) {
                    r3a[0][2*p][m]   = fmaf(v0[ul][m], d0, r3a[0][2*p][m]);
                    r3a[0][2*p+1][m] = fmaf(v0[ul][m], d1, r3a[0][2*p+1][m]);
                    r3a[1][2*p][m]   = fmaf(v1[ul][m], d2, r3a[1][2*p][m]);
                    r3a[1][2*p+1][m] = fmaf(v1[ul][m], d3, r3a[1][2*p+1][m]);
                }
            }
            if (c == 15) {
                int dns[2] = {((int*)(sm + DST_OFF))[r0], ((int*)(sm + DST_OFF))[r1]};
                int ers[2] = {r0, r1};
#pragma unroll
                for (int ei = 0; ei < 2; ei++) {
                    float s1m[3];
#pragma unroll
                    for (int m = 0; m < 3; m++) s1m[m] = sm[SH1_OFF + ers[ei] * 3 + m];
                    float* op = out + (size_t)dns[ei] * 64 + 16;
                    float va[4][3];
#pragma unroll
                    for (int s = 0; s < 4; s++)
#pragma unroll
                        for (int m = 0; m < 3; m++)
                            va[s][m] = ALPHA * fmaf(s1m[m], r2a[ei][s], r3a[ei][s][m]);
                    red2(op + 6*qq + 0, va[0][0], va[0][1]);
                    red2(op + 6*qq + 2, va[0][2], va[1][0]);
                    red2(op + 6*qq + 4, va[1][1], va[1][2]);
                    red2(op + 6*qq + 24, va[2][0], va[2][1]);
                    red2(op + 6*qq + 26, va[2][2], va[3][0]);
                    red2(op + 6*qq + 28, va[3][1], va[3][2]);
                }
            }
        }
        cpwait0();
        __syncthreads();
    }
}

// ---------------------------------------------------------------------------
extern "C" void kernel_launch(void* const* d_in, const int* in_sizes, int n_in,
                              void* d_out, int out_size) {
    const float* xfeat = (const float*)d_in[0];
    const float* eshv  = (const float*)d_in[1];
    const float* emb   = (const float*)d_in[2];
    const float* W1    = (const float*)d_in[3];
    const float* b1    = (const float*)d_in[4];
    const float* W2    = (const float*)d_in[5];
    const float* b2    = (const float*)d_in[6];
    const int*   src   = (const int*)d_in[7];
    const int*   dstp  = (const int*)d_in[8];
    float* out = (float*)d_out;

    cudaFuncSetAttribute(k_fused, cudaFuncAttributeMaxDynamicSharedMemorySize, SMEM_BYTES);

    k_zero<<<(NNODES * 64 + 255) / 256, 256>>>(out);
    k_prep<<<(16384 + 131072 + 255) / 256, 256>>>(W1, W2);
    k_fused<<<E_TOTAL / EPB, 256, SMEM_BYTES>>>(xfeat, eshv, emb, b1, b2, src, dstp, out);
    k_norm<<<(NNODES * 64 + 255) / 256, 256>>>(out);
}

// round 7
// speedup vs baseline: 6.9545x; 1.0944x over previous
#include <cuda_runtime.h>
#include <cuda_fp16.h>
#include <math.h>
#include <cstdint>

#define E_TOTAL 160000
#define NNODES  10000
#define EPB     128
#define INV_SQRT3 0.5773502691896258f
#define ALPHA     0.17677669529663687f

// ---- smem float offsets ----
// HS: 128 rows x 136 halves (emb->h tile, fp16) = [0, 8704)
#define WS_OFF   8704     // 2 x 16KB W fragment buffers (fp16)
#define CS1_OFF  16896    // [128][17] f32: INV_SQRT3*(v . sh1)
#define SV_OFF   19072    // [128][17] f32: raw s
#define VV_OFF   21248    // [128][49] f32: raw v (3u+m)
#define SH_OFF   27520    // [128][4]  f32: edge_sh (sh0, s1x, s1y, s1z)
#define DST_OFF  28032    // [128] int
#define TOTF     28160
#define SMEM_BYTES (TOTF * 4)   // 112640 B -> 2 CTAs/SM

// fragment-ordered fp16 weights: [blk][nt][kt(8)][lane][pair][hh]
__device__ __align__(16) __half g_W1F[16384];        // 32KB
__device__ __align__(16) __half g_W2F[16 * 8192];    // 16 chunks x 16KB
__device__ float g_cnt[NNODES];

__device__ __forceinline__ float gelu_exact(float x) {
    return 0.5f * x * (1.0f + erff(x * 0.7071067811865476f));
}
__device__ __forceinline__ void red2(float* p, float a, float b) {
    asm volatile("red.global.add.v2.f32 [%0], {%1, %2};"
                 :: "l"(p), "f"(a), "f"(b) : "memory");
}
__device__ __forceinline__ void mma16(float* c, const unsigned* a,
                                      unsigned b0, unsigned b1) {
    asm("mma.sync.aligned.m16n8k16.row.col.f32.f16.f16.f32 "
        "{%0,%1,%2,%3}, {%4,%5,%6,%7}, {%8,%9}, {%0,%1,%2,%3};"
        : "+f"(c[0]), "+f"(c[1]), "+f"(c[2]), "+f"(c[3])
        : "r"(a[0]), "r"(a[1]), "r"(a[2]), "r"(a[3]), "r"(b0), "r"(b1));
}
__device__ __forceinline__ void cpasync16(uint32_t s, const void* g) {
    asm volatile("cp.async.cg.shared.global [%0], [%1], 16;" :: "r"(s), "l"(g));
}
__device__ __forceinline__ void cpcommit() {
    asm volatile("cp.async.commit_group;" ::: "memory");
}
__device__ __forceinline__ void cpwait0() {
    asm volatile("cp.async.wait_group 0;" ::: "memory");
}

// ---------------- prep: fp16 weights in m16n8k16 fragment order ----------------
__global__ void k_prep(const float* __restrict__ W1, const float* __restrict__ W2) {
    int i = blockIdx.x * 256 + threadIdx.x;
    if (i < 16384) {
        int hh = i & 1, pair = (i >> 1) & 1, lane = (i >> 2) & 31;
        int kt = (i >> 7) & 7, nt = (i >> 10) & 7, h = (i >> 13) & 1;
        int q = lane & 3, g = lane >> 2;
        int k = kt * 16 + pair * 8 + 2 * q + hh, n = h * 64 + nt * 8 + g;
        g_W1F[i] = __float2half_rn(W1[k * 128 + n]);
    } else if (i < 16384 + 131072) {
        int j = i - 16384;
        int hh = j & 1, pair = (j >> 1) & 1, lane = (j >> 2) & 31;
        int kt = (j >> 7) & 7, nt = (j >> 10) & 7, c = (j >> 13) & 15;
        int q = lane & 3, g = lane >> 2;
        int k = kt * 16 + pair * 8 + 2 * q + hh, col = c * 64 + nt * 8 + g;
        g_W2F[j] = __float2half_rn(W2[k * 1024 + col]);
    }
}

__global__ void k_zero(float* __restrict__ out) {
    int i = blockIdx.x * blockDim.x + threadIdx.x;
    if (i < NNODES * 64) out[i] = 0.0f;
    if (i < NNODES) g_cnt[i] = 0.0f;
}
__global__ void k_norm(float* __restrict__ out) {
    int i = blockIdx.x * blockDim.x + threadIdx.x;
    if (i < NNODES * 64) out[i] = out[i] / fmaxf(g_cnt[i >> 6], 1.0f);
}

// ---------------- fused kernel ----------------
__global__ void __launch_bounds__(256, 2)
k_fused(const float* __restrict__ xfeat, const float* __restrict__ esh,
        const float* __restrict__ emb, const float* __restrict__ b1,
        const float* __restrict__ b2, const int* __restrict__ src,
        const int* __restrict__ dstp, float* __restrict__ out) {
    extern __shared__ float sm[];
    __half* hs = (__half*)sm;                    // 128 x 136 halves
    char* wsc = (char*)(sm + WS_OFF);
    const uint32_t wsb = (uint32_t)__cvta_generic_to_shared(wsc);
    const int tid = threadIdx.x, wid = tid >> 5, lane = tid & 31;
    const int qq = lane & 3, gg = lane >> 2;
    const int eBase = blockIdx.x * EPB;
    const int r0 = 16 * wid + gg, r1 = r0 + 8;

    // ---- stage emb tile as fp16 ----
#pragma unroll
    for (int it = 0; it < 16; it++) {
        int qi = it * 256 + tid;
        int rr = qi >> 5, c4 = qi & 31;
        float4 v = *(const float4*)(emb + (size_t)(eBase + rr) * 128 + 4 * c4);
        __half2 p0 = __floats2half2_rn(v.x, v.y);
        __half2 p1 = __floats2half2_rn(v.z, v.w);
        uint2 pk = {*(unsigned*)&p0, *(unsigned*)&p1};
        *(uint2*)((char*)hs + rr * 272 + 8 * c4) = pk;
    }
    // ---- stage W1F (32KB) via cp.async ----
#pragma unroll
    for (int it = 0; it < 8; it++)
        cpasync16(wsb + (it * 256 + tid) * 16, (const char*)g_W1F + (it * 256 + tid) * 16);
    cpcommit();

    // ---- per-edge TP coefficients (2 threads / edge) ----
    {
        int e = tid >> 1, ge = eBase + e, u0 = (tid & 1) * 8;
        int si = __ldg(src + ge);
        const float* x = xfeat + (size_t)si * 64;
        float4 shv = *(const float4*)(esh + (size_t)ge * 4);
        float s1x = shv.y, s1y = shv.z, s1z = shv.w;
        float4 aq = *(const float4*)(x + u0), bq = *(const float4*)(x + u0 + 4);
        float sv[8] = {aq.x, aq.y, aq.z, aq.w, bq.x, bq.y, bq.z, bq.w};
        float vv[24];
#pragma unroll
        for (int p = 0; p < 6; p++) {
            float4 t = *(const float4*)(x + 16 + 3 * u0 + 4 * p);
            vv[4*p] = t.x; vv[4*p+1] = t.y; vv[4*p+2] = t.z; vv[4*p+3] = t.w;
        }
#pragma unroll
        for (int du = 0; du < 8; du++) {
            int u = u0 + du;
            float v0 = vv[3*du], v1 = vv[3*du+1], v2 = vv[3*du+2];
            sm[SV_OFF + e * 17 + u] = sv[du];
            sm[CS1_OFF + e * 17 + u] = INV_SQRT3 * (v0 * s1x + v1 * s1y + v2 * s1z);
            sm[VV_OFF + e * 49 + 3 * u + 0] = v0;
            sm[VV_OFF + e * 49 + 3 * u + 1] = v1;
            sm[VV_OFF + e * 49 + 3 * u + 2] = v2;
        }
        if ((tid & 1) == 0) {
            *(float4*)(sm + SH_OFF + e * 4) = shv;
            ((int*)(sm + DST_OFF))[e] = __ldg(dstp + ge);
        }
    }
    cpwait0();
    __syncthreads();

    // ---- A fragments (fp16 rows of this warp) ----
    unsigned a[8][4];
#pragma unroll
    for (int kt = 0; kt < 8; kt++) {
        a[kt][0] = *(const unsigned*)((char*)hs + r0 * 272 + kt * 32 + 4 * qq);
        a[kt][1] = *(const unsigned*)((char*)hs + r1 * 272 + kt * 32 + 4 * qq);
        a[kt][2] = *(const unsigned*)((char*)hs + r0 * 272 + kt * 32 + 4 * qq + 16);
        a[kt][3] = *(const unsigned*)((char*)hs + r1 * 272 + kt * 32 + 4 * qq + 16);
    }

    // ---- GEMM1: two 64-col halves, bias in acc init, gelu -> h over emb ----
#pragma unroll
    for (int h = 0; h < 2; h++) {
        float acc[8][4];
#pragma unroll
        for (int nt = 0; nt < 8; nt++) {
            float2 bb = *(const float2*)(b1 + h * 64 + nt * 8 + 2 * qq);
            acc[nt][0] = bb.x; acc[nt][1] = bb.y;
            acc[nt][2] = bb.x; acc[nt][3] = bb.y;
        }
        const uint2* wb = (const uint2*)(wsc + h * 16384);
#pragma unroll
        for (int kt = 0; kt < 8; kt++)
#pragma unroll
            for (int nt = 0; nt < 8; nt++) {
                uint2 b = wb[(nt * 8 + kt) * 32 + lane];
                mma16(acc[nt], a[kt], b.x, b.y);
            }
#pragma unroll
        for (int nt = 0; nt < 8; nt++) {
            int col = h * 64 + nt * 8 + 2 * qq;
            __half2 h0 = __floats2half2_rn(gelu_exact(acc[nt][0]), gelu_exact(acc[nt][1]));
            __half2 h1 = __floats2half2_rn(gelu_exact(acc[nt][2]), gelu_exact(acc[nt][3]));
            *(__half2*)((char*)hs + r0 * 272 + col * 2) = h0;
            *(__half2*)((char*)hs + r1 * 272 + col * 2) = h1;
        }
    }
    __syncwarp();
    // reload A fragments = h
#pragma unroll
    for (int kt = 0; kt < 8; kt++) {
        a[kt][0] = *(const unsigned*)((char*)hs + r0 * 272 + kt * 32 + 4 * qq);
        a[kt][1] = *(const unsigned*)((char*)hs + r1 * 272 + kt * 32 + 4 * qq);
        a[kt][2] = *(const unsigned*)((char*)hs + r0 * 272 + kt * 32 + 4 * qq + 16);
        a[kt][3] = *(const unsigned*)((char*)hs + r1 * 272 + kt * 32 + 4 * qq + 16);
    }
    __syncthreads();   // all warps done with W1F

    // per-thread edge scalars
    const float sh0_0 = sm[SH_OFF + r0 * 4], sh0_1 = sm[SH_OFF + r1 * 4];

    // ---- stage W2 chunk 0 ----
#pragma unroll
    for (int it = 0; it < 4; it++)
        cpasync16(wsb + (it * 256 + tid) * 16, (const char*)g_W2F + (it * 256 + tid) * 16);
    cpcommit();
    cpwait0();
    __syncthreads();

    float r0a[2][4], r2a[2][4], r3a[2][4][3];
#pragma unroll
    for (int ei = 0; ei < 2; ei++)
#pragma unroll
        for (int s = 0; s < 4; s++) {
            r0a[ei][s] = 0.0f; r2a[ei][s] = 0.0f;
            r3a[ei][s][0] = 0.0f; r3a[ei][s][1] = 0.0f; r3a[ei][s][2] = 0.0f;
        }

#pragma unroll 1
    for (int c = 0; c < 16; c++) {
        if (c < 15) {   // prefetch next chunk
#pragma unroll
            for (int it = 0; it < 4; it++)
                cpasync16(wsb + ((c + 1) & 1) * 16384 + (it * 256 + tid) * 16,
                          (const char*)g_W2F + (c + 1) * 16384 + (it * 256 + tid) * 16);
            cpcommit();
        }
        const uint2* wb = (const uint2*)(wsc + (c & 1) * 16384);
        const int t = c >> 2, g4 = c & 3;

#pragma unroll
        for (int half = 0; half < 2; half++) {
            float acc[4][4];
#pragma unroll
            for (int ntl = 0; ntl < 4; ntl++) {
                int nt = half * 4 + ntl;
                float2 bb = *(const float2*)(b2 + c * 64 + nt * 8 + 2 * qq);
                acc[ntl][0] = bb.x; acc[ntl][1] = bb.y;
                acc[ntl][2] = bb.x; acc[ntl][3] = bb.y;
            }
#pragma unroll
            for (int kt = 0; kt < 8; kt++)
#pragma unroll
                for (int ntl = 0; ntl < 4; ntl++) {
                    uint2 b = wb[((half * 4 + ntl) * 8 + kt) * 32 + lane];
                    mma16(acc[ntl], a[kt], b.x, b.y);
                }

            if (t <= 2) {
                float cc0[2], cc1[2];
#pragma unroll
                for (int i = 0; i < 2; i++) {
                    int u = 4 * g4 + half * 2 + i;
                    if (t == 0) {
                        cc0[i] = sh0_0 * sm[SV_OFF + r0 * 17 + u];
                        cc1[i] = sh0_1 * sm[SV_OFF + r1 * 17 + u];
                    } else if (t == 1) {
                        cc0[i] = sm[CS1_OFF + r0 * 17 + u];
                        cc1[i] = sm[CS1_OFF + r1 * 17 + u];
                    } else {
                        cc0[i] = sm[SV_OFF + r0 * 17 + u];
                        cc1[i] = sm[SV_OFF + r1 * 17 + u];
                    }
                }
                float (*ra)[4] = (t == 2) ? r2a : r0a;
#pragma unroll
                for (int ntl = 0; ntl < 4; ntl++) {
                    int i = ntl >> 1, p = ntl & 1;
                    ra[0][2*p]   = fmaf(cc0[i], acc[ntl][0], ra[0][2*p]);
                    ra[0][2*p+1] = fmaf(cc0[i], acc[ntl][1], ra[0][2*p+1]);
                    ra[1][2*p]   = fmaf(cc1[i], acc[ntl][2], ra[1][2*p]);
                    ra[1][2*p+1] = fmaf(cc1[i], acc[ntl][3], ra[1][2*p+1]);
                }
            } else {
                float v0[2][3], v1[2][3];
#pragma unroll
                for (int i = 0; i < 2; i++)
#pragma unroll
                    for (int m = 0; m < 3; m++) {
                        int u = 4 * g4 + half * 2 + i;
                        v0[i][m] = sm[VV_OFF + r0 * 49 + 3 * u + m];
                        v1[i][m] = sm[VV_OFF + r1 * 49 + 3 * u + m];
                    }
#pragma unroll
                for (int ntl = 0; ntl < 4; ntl++) {
                    int i = ntl >> 1, p = ntl & 1;
                    float d0 = sh0_0 * acc[ntl][0], d1 = sh0_0 * acc[ntl][1];
                    float d2 = sh0_1 * acc[ntl][2], d3 = sh0_1 * acc[ntl][3];
#pragma unroll
                    for (int m = 0; m < 3; m++) {
                        r3a[0][2*p][m]   = fmaf(v0[i][m], d0, r3a[0][2*p][m]);
                        r3a[0][2*p+1][m] = fmaf(v0[i][m], d1, r3a[0][2*p+1][m]);
                        r3a[1][2*p][m]   = fmaf(v1[i][m], d2, r3a[1][2*p][m]);
                        r3a[1][2*p+1][m] = fmaf(v1[i][m], d3, r3a[1][2*p+1][m]);
                    }
                }
            }
        }

        if (c == 7) {   // scatter out0
            int dn0 = ((int*)(sm + DST_OFF))[r0];
            int dn1 = ((int*)(sm + DST_OFF))[r1];
            float* op0 = out + (size_t)dn0 * 64;
            float* op1 = out + (size_t)dn1 * 64;
            red2(op0 + 2*qq,     ALPHA * r0a[0][0], ALPHA * r0a[0][1]);
            red2(op0 + 2*qq + 8, ALPHA * r0a[0][2], ALPHA * r0a[0][3]);
            red2(op1 + 2*qq,     ALPHA * r0a[1][0], ALPHA * r0a[1][1]);
            red2(op1 + 2*qq + 8, ALPHA * r0a[1][2], ALPHA * r0a[1][3]);
            if (qq == 0) {
                atomicAdd(&g_cnt[dn0], 1.0f);
                atomicAdd(&g_cnt[dn1], 1.0f);
            }
        }
        if (c == 15) {  // scatter out1
            int dns[2] = {((int*)(sm + DST_OFF))[r0], ((int*)(sm + DST_OFF))[r1]};
            int ers[2] = {r0, r1};
#pragma unroll
            for (int ei = 0; ei < 2; ei++) {
                float s1m[3];
#pragma unroll
                for (int m = 0; m < 3; m++) s1m[m] = sm[SH_OFF + ers[ei] * 4 + 1 + m];
                float* op = out + (size_t)dns[ei] * 64 + 16;
                float va[4][3];
#pragma unroll
                for (int s = 0; s < 4; s++)
#pragma unroll
                    for (int m = 0; m < 3; m++)
                        va[s][m] = ALPHA * fmaf(s1m[m], r2a[ei][s], r3a[ei][s][m]);
                red2(op + 6*qq + 0, va[0][0], va[0][1]);
                red2(op + 6*qq + 2, va[0][2], va[1][0]);
                red2(op + 6*qq + 4, va[1][1], va[1][2]);
                red2(op + 6*qq + 24, va[2][0], va[2][1]);
                red2(op + 6*qq + 26, va[2][2], va[3][0]);
                red2(op + 6*qq + 28, va[3][1], va[3][2]);
            }
        }
        cpwait0();
        __syncthreads();
    }
}

// ---------------------------------------------------------------------------
extern "C" void kernel_launch(void* const* d_in, const int* in_sizes, int n_in,
                              void* d_out, int out_size) {
    const float* xfeat = (const float*)d_in[0];
    const float* eshv  = (const float*)d_in[1];
    const float* emb   = (const float*)d_in[2];
    const float* W1    = (const float*)d_in[3];
    const float* b1    = (const float*)d_in[4];
    const float* W2    = (const float*)d_in[5];
    const float* b2    = (const float*)d_in[6];
    const int*   src   = (const int*)d_in[7];
    const int*   dstp  = (const int*)d_in[8];
    float* out = (float*)d_out;

    cudaFuncSetAttribute(k_fused, cudaFuncAttributeMaxDynamicSharedMemorySize, SMEM_BYTES);

    k_zero<<<(NNODES * 64 + 255) / 256, 256>>>(out);
    k_prep<<<(16384 + 131072 + 255) / 256, 256>>>(W1, W2);
    k_fused<<<E_TOTAL / EPB, 256, SMEM_BYTES>>>(xfeat, eshv, emb, b1, b2, src, dstp, out);
    k_norm<<<(NNODES * 64 + 255) / 256, 256>>>(out);
}